// round 1
// baseline (speedup 1.0000x reference)
#include <cuda_runtime.h>
#include <math.h>

#define H 128
#define NCHK 8000
#define NVAR 16000
#define NITER 10
#define LN_EPS 1e-6f

// ---------------- scratch (device globals; no runtime allocation) ----------------
__device__ float g_hc[NCHK * H];
__device__ float g_hv[NVAR * H];
__device__ float g_aggc[NCHK * H];
__device__ float g_aggv[NVAR * H];
__device__ float g_updc[NCHK * H];
__device__ float g_updv[NVAR * H];

__device__ __forceinline__ float elu_f(float x) { return x > 0.f ? x : expm1f(x); }

// ---------------- init: h = LN(0.1*feat * Win + bin) ----------------
__global__ void init_kernel(const float* __restrict__ feat, const float* __restrict__ Win,
                            const float* __restrict__ bin, const float* __restrict__ g,
                            const float* __restrict__ bln, float* __restrict__ h)
{
    __shared__ float red[4];
    __shared__ float red2[4];
    const int n = blockIdx.x;
    const int j = threadIdx.x;
    const float x = 0.1f * feat[n];
    const float val = x * Win[j] + bin[j];

    float s = val;
    #pragma unroll
    for (int o = 16; o > 0; o >>= 1) s += __shfl_xor_sync(0xffffffff, s, o);
    if ((j & 31) == 0) red[j >> 5] = s;
    __syncthreads();
    const float m = (red[0] + red[1] + red[2] + red[3]) * (1.0f / 128.0f);

    const float d = val - m;
    float s2 = d * d;
    #pragma unroll
    for (int o = 16; o > 0; o >>= 1) s2 += __shfl_xor_sync(0xffffffff, s2, o);
    if ((j & 31) == 0) red2[j >> 5] = s2;
    __syncthreads();
    const float v = (red2[0] + red2[1] + red2[2] + red2[3]) * (1.0f / 128.0f);

    h[(size_t)n * H + j] = g[j] * d * rsqrtf(v + LN_EPS) + bln[j];
}

// ---------------- generic [rows x 256] @ [256 x 128] + bias, ELU epilogue ----------------
// SCATTER=true : rows are edges; A = concat(A0[src[e]], A1[tgt[e]]); atomicAdd into out[tgt[e]]
// SCATTER=false: rows are nodes; A = concat(A0[node],  A1[node]);  store to out[node]
// Layout: 32 rows/block, 128 threads; thread (eg=tid/32, jg=tid%32) computes 8 rows x 4 cols.
// XsT is the gathered A tile stored transposed [k][row] (stride 36 for alignment),
// so the inner loop is 3x LDS.128 + 32 FFMA per k -> FMA-pipe bound.
#define XT_STRIDE 36
#define GEMM_SMEM_BYTES ((256 * XT_STRIDE + 64 * 128) * 4 + 64 * 4)

template <bool SCATTER>
__global__ void __launch_bounds__(128)
gemm256_kernel(const float* __restrict__ A0, const float* __restrict__ A1,
               const int* __restrict__ src, const int* __restrict__ tgt,
               const float* __restrict__ W, const float* __restrict__ bias,
               float* __restrict__ out, int nRows)
{
    extern __shared__ float sm[];
    float* XsT = sm;                       // 256 x XT_STRIDE
    float* Ws  = sm + 256 * XT_STRIDE;     // 64 x 128
    int*   s_src = (int*)(Ws + 64 * 128);  // 32
    int*   s_tgt = s_src + 32;             // 32

    const int tid = threadIdx.x;
    const int rb  = blockIdx.x * 32;

    if (SCATTER) {
        if (tid < 32) {
            int r = rb + tid;
            if (r >= nRows) r = 0;         // clamp; epilogue skips OOB rows
            s_src[tid] = src[r];
            s_tgt[tid] = tgt[r];
        }
        __syncthreads();
    }

    // gather tile (transposed into SMEM)
    for (int idx = tid; idx < 32 * 256; idx += 128) {
        const int e = idx >> 8;
        const int k = idx & 255;
        float v;
        if (SCATTER) {
            v = (k < 128) ? A0[(size_t)s_src[e] * H + k]
                          : A1[(size_t)s_tgt[e] * H + (k - 128)];
        } else {
            int node = rb + e;
            if (node >= nRows) node = nRows - 1;
            v = (k < 128) ? A0[(size_t)node * H + k]
                          : A1[(size_t)node * H + (k - 128)];
        }
        XsT[k * XT_STRIDE + e] = v;
    }
    __syncthreads();

    float acc[8][4];
    #pragma unroll
    for (int i = 0; i < 8; i++)
        #pragma unroll
        for (int c = 0; c < 4; c++) acc[i][c] = 0.f;

    const int jg = tid & 31;   // column group: cols 4*jg..4*jg+3
    const int eg = tid >> 5;   // row group  : rows 8*eg..8*eg+7

    for (int k0 = 0; k0 < 256; k0 += 64) {
        for (int idx = tid; idx < 64 * 128; idx += 128)
            Ws[idx] = W[(size_t)(k0 + (idx >> 7)) * H + (idx & 127)];
        __syncthreads();

        #pragma unroll 8
        for (int kk = 0; kk < 64; kk++) {
            const float4 w  = *(const float4*)&Ws[kk * 128 + 4 * jg];
            const float4 xa = *(const float4*)&XsT[(k0 + kk) * XT_STRIDE + 8 * eg];
            const float4 xb = *(const float4*)&XsT[(k0 + kk) * XT_STRIDE + 8 * eg + 4];
            const float xv[8] = {xa.x, xa.y, xa.z, xa.w, xb.x, xb.y, xb.z, xb.w};
            #pragma unroll
            for (int i = 0; i < 8; i++) {
                acc[i][0] += xv[i] * w.x;
                acc[i][1] += xv[i] * w.y;
                acc[i][2] += xv[i] * w.z;
                acc[i][3] += xv[i] * w.w;
            }
        }
        __syncthreads();
    }

    const float4 bv = *(const float4*)&bias[4 * jg];
    #pragma unroll
    for (int i = 0; i < 8; i++) {
        const int e = 8 * eg + i;
        const int r = rb + e;
        if (r >= nRows) break;
        float v0 = elu_f(acc[i][0] + bv.x);
        float v1 = elu_f(acc[i][1] + bv.y);
        float v2 = elu_f(acc[i][2] + bv.z);
        float v3 = elu_f(acc[i][3] + bv.w);
        if (SCATTER) {
            float* dst = out + (size_t)s_tgt[e] * H + 4 * jg;
            atomicAdd(dst + 0, v0);
            atomicAdd(dst + 1, v1);
            atomicAdd(dst + 2, v2);
            atomicAdd(dst + 3, v3);
        } else {
            float4 o = make_float4(v0, v1, v2, v3);
            *(float4*)(out + (size_t)r * H + 4 * jg) = o;
        }
    }
}

// ---------------- GRU (Keras reset_after=True): h <- GRU(x=upd, h) ----------------
// 8 nodes/block, 128 threads; thread j computes z,r,hh columns (j, j+128, j+256)
// of xa = x@Wg and ha = h@Ug for all 8 nodes -> 48 accumulators.
__global__ void __launch_bounds__(128)
gru_kernel(const float* __restrict__ upd, float* __restrict__ h,
           const float* __restrict__ Wg, const float* __restrict__ Ug,
           const float* __restrict__ bg, int nNodes)
{
    __shared__ float XsT[128 * 12];
    __shared__ float HsT[128 * 12];
    const int tid = threadIdx.x;
    const int nb  = blockIdx.x * 8;

    for (int idx = tid; idx < 8 * 128; idx += 128) {
        const int e = idx >> 7;
        const int k = idx & 127;
        int node = nb + e;
        if (node >= nNodes) node = nNodes - 1;
        XsT[k * 12 + e] = upd[(size_t)node * H + k];
        HsT[k * 12 + e] = h[(size_t)node * H + k];
    }
    __syncthreads();

    float xaz[8], xar[8], xah[8], haz[8], har[8], hah[8];
    #pragma unroll
    for (int i = 0; i < 8; i++) { xaz[i]=xar[i]=xah[i]=haz[i]=har[i]=hah[i]=0.f; }

    const int j = tid;
    #pragma unroll 4
    for (int k = 0; k < 128; k++) {
        const float4 x0 = *(const float4*)&XsT[k * 12];
        const float4 x1 = *(const float4*)&XsT[k * 12 + 4];
        const float4 h0 = *(const float4*)&HsT[k * 12];
        const float4 h1 = *(const float4*)&HsT[k * 12 + 4];
        const float wz = Wg[(size_t)k * 384 + j];
        const float wr = Wg[(size_t)k * 384 + 128 + j];
        const float wh = Wg[(size_t)k * 384 + 256 + j];
        const float uz = Ug[(size_t)k * 384 + j];
        const float ur = Ug[(size_t)k * 384 + 128 + j];
        const float uh = Ug[(size_t)k * 384 + 256 + j];
        const float xv[8] = {x0.x, x0.y, x0.z, x0.w, x1.x, x1.y, x1.z, x1.w};
        const float hv8[8] = {h0.x, h0.y, h0.z, h0.w, h1.x, h1.y, h1.z, h1.w};
        #pragma unroll
        for (int n = 0; n < 8; n++) {
            xaz[n] += xv[n] * wz;
            xar[n] += xv[n] * wr;
            xah[n] += xv[n] * wh;
            haz[n] += hv8[n] * uz;
            har[n] += hv8[n] * ur;
            hah[n] += hv8[n] * uh;
        }
    }

    const float b0z = bg[j],        b0r = bg[128 + j],        b0h = bg[256 + j];
    const float b1z = bg[384 + j],  b1r = bg[384 + 128 + j],  b1h = bg[384 + 256 + j];

    #pragma unroll
    for (int n = 0; n < 8; n++) {
        const int node = nb + n;
        if (node >= nNodes) break;
        const float z = 1.f / (1.f + expf(-(xaz[n] + b0z + haz[n] + b1z)));
        const float r = 1.f / (1.f + expf(-(xar[n] + b0r + har[n] + b1r)));
        const float cand = tanhf(xah[n] + b0h + r * (hah[n] + b1h));
        const float hold = HsT[j * 12 + n];
        h[(size_t)node * H + j] = z * hold + (1.f - z) * cand;
    }
}

// ---------------- final: out[n] = hv[n] . Wf + bf ----------------
__global__ void final_kernel(const float* __restrict__ hv, const float* __restrict__ Wf,
                             const float* __restrict__ bf, float* __restrict__ out, int n)
{
    const int gw = (blockIdx.x * blockDim.x + threadIdx.x) >> 5;
    const int lane = threadIdx.x & 31;
    if (gw >= n) return;
    const float* row = hv + (size_t)gw * H;
    float s = row[lane] * Wf[lane] + row[lane + 32] * Wf[lane + 32]
            + row[lane + 64] * Wf[lane + 64] + row[lane + 96] * Wf[lane + 96];
    #pragma unroll
    for (int o = 16; o > 0; o >>= 1) s += __shfl_xor_sync(0xffffffff, s, o);
    if (lane == 0) out[gw] = s + bf[0];
}

// ---------------- host ----------------
extern "C" void kernel_launch(void* const* d_in, const int* in_sizes, int n_in,
                              void* d_out, int out_size)
{
    const float* check_feats = (const float*)d_in[0];
    const float* var_feats   = (const float*)d_in[1];
    const int*   c2v_src     = (const int*)d_in[2];
    const int*   c2v_tgt     = (const int*)d_in[3];
    const int*   v2c_src     = (const int*)d_in[4];
    const int*   v2c_tgt     = (const int*)d_in[5];
    const float* Wc_in  = (const float*)d_in[6];
    const float* bc_in  = (const float*)d_in[7];
    const float* Wv_in  = (const float*)d_in[8];
    const float* bv_in  = (const float*)d_in[9];
    const float* gc_ln  = (const float*)d_in[10];
    const float* bc_ln  = (const float*)d_in[11];
    const float* gv_ln  = (const float*)d_in[12];
    const float* bv_ln  = (const float*)d_in[13];
    const float* Wmsg_c = (const float*)d_in[14];
    const float* bmsg_c = (const float*)d_in[15];
    const float* Wmsg_v = (const float*)d_in[16];
    const float* bmsg_v = (const float*)d_in[17];
    const float* Wns_c  = (const float*)d_in[18];
    const float* bns_c  = (const float*)d_in[19];
    const float* Wns_v  = (const float*)d_in[20];
    const float* bns_v  = (const float*)d_in[21];
    const float* Wg_c   = (const float*)d_in[22];
    const float* Ug_c   = (const float*)d_in[23];
    const float* bg_c   = (const float*)d_in[24];
    const float* Wg_v   = (const float*)d_in[25];
    const float* Ug_v   = (const float*)d_in[26];
    const float* bg_v   = (const float*)d_in[27];
    const float* Wf     = (const float*)d_in[28];
    const float* bf     = (const float*)d_in[29];

    const int NCn = in_sizes[0];  // 8000
    const int NVn = in_sizes[1];  // 16000
    const int E   = in_sizes[2];  // 60000

    float *hc, *hv, *aggc, *aggv, *updc, *updv;
    cudaGetSymbolAddress((void**)&hc,   g_hc);
    cudaGetSymbolAddress((void**)&hv,   g_hv);
    cudaGetSymbolAddress((void**)&aggc, g_aggc);
    cudaGetSymbolAddress((void**)&aggv, g_aggv);
    cudaGetSymbolAddress((void**)&updc, g_updc);
    cudaGetSymbolAddress((void**)&updv, g_updv);

    cudaFuncSetAttribute(gemm256_kernel<true>,  cudaFuncAttributeMaxDynamicSharedMemorySize, GEMM_SMEM_BYTES);
    cudaFuncSetAttribute(gemm256_kernel<false>, cudaFuncAttributeMaxDynamicSharedMemorySize, GEMM_SMEM_BYTES);

    init_kernel<<<NCn, 128>>>(check_feats, Wc_in, bc_in, gc_ln, bc_ln, hc);
    init_kernel<<<NVn, 128>>>(var_feats,  Wv_in, bv_in, gv_ln, bv_ln, hv);

    const int gE  = (E + 31) / 32;
    const int gNC = (NCn + 31) / 32;
    const int gNV = (NVn + 31) / 32;

    for (int it = 0; it < NITER; it++) {
        cudaMemsetAsync(aggc, 0, (size_t)NCn * H * sizeof(float), 0);
        cudaMemsetAsync(aggv, 0, (size_t)NVn * H * sizeof(float), 0);

        // v->c messages: concat(hv[v2c_src], hc[v2c_tgt]) @ Wmsg_c -> scatter into agg_c
        gemm256_kernel<true><<<gE, 128, GEMM_SMEM_BYTES>>>(
            hv, hc, v2c_src, v2c_tgt, Wmsg_c, bmsg_c, aggc, E);
        // c->v messages
        gemm256_kernel<true><<<gE, 128, GEMM_SMEM_BYTES>>>(
            hc, hv, c2v_src, c2v_tgt, Wmsg_v, bmsg_v, aggv, E);

        // node updates: elu(concat(h, agg) @ Wns + b)
        gemm256_kernel<false><<<gNC, 128, GEMM_SMEM_BYTES>>>(
            hc, aggc, nullptr, nullptr, Wns_c, bns_c, updc, NCn);
        gemm256_kernel<false><<<gNV, 128, GEMM_SMEM_BYTES>>>(
            hv, aggv, nullptr, nullptr, Wns_v, bns_v, updv, NVn);

        // GRU state updates (in place)
        gru_kernel<<<(NCn + 7) / 8, 128>>>(updc, hc, Wg_c, Ug_c, bg_c, NCn);
        gru_kernel<<<(NVn + 7) / 8, 128>>>(updv, hv, Wg_v, Ug_v, bg_v, NVn);
    }

    final_kernel<<<(NVn * 32 + 127) / 128, 128>>>(hv, Wf, bf, (float*)d_out, NVn);
}

// round 2
// speedup vs baseline: 1.5157x; 1.5157x over previous
#include <cuda_runtime.h>
#include <math.h>

#define H 128
#define NCHK 8000
#define NVAR 16000
#define EDGES 60000
#define NITER 10
#define LN_EPS 1e-6f

typedef unsigned long long u64;

// ---------------- scratch (device globals; no runtime allocation) ----------------
__device__ float g_hc[NCHK * H];
__device__ float g_hv[NVAR * H];
__device__ float g_Pc[NCHK * 256];     // [0:128) sender-proj (c2v), [128:256) receiver-proj (v2c)
__device__ float g_Pv[NVAR * 256];     // [0:128) sender-proj (v2c), [128:256) receiver-proj (c2v)
__device__ float g_aggc[NCHK * H];
__device__ float g_aggv[NVAR * H];
__device__ float g_updc[NCHK * H];
__device__ float g_updv[NVAR * H];
__device__ float g_xac[NCHK * 384];
__device__ float g_hac[NCHK * 384];
__device__ float g_xav[NVAR * 384];
__device__ float g_hav[NVAR * 384];
// CSR scratch
__device__ int g_cnt_c[NCHK], g_cnt_v[NVAR];
__device__ int g_rp_c[NCHK + 1], g_rp_v[NVAR + 1];
__device__ int g_cur_c[NCHK], g_cur_v[NVAR];
__device__ int g_el_c[EDGES], g_el_v[EDGES];

__device__ __forceinline__ float elu_f(float x) { return x > 0.f ? x : expm1f(x); }
__device__ __forceinline__ float sig_f(float x) { return 1.f / (1.f + expf(-x)); }

__device__ __forceinline__ u64 pack2(float lo, float hi) {
    u64 p;
    asm("mov.b64 %0, {%1, %2};" : "=l"(p) : "f"(lo), "f"(hi));
    return p;
}
__device__ __forceinline__ void fma2(u64& d, u64 a, u64 b) {
    asm("fma.rn.f32x2 %0, %1, %2, %0;" : "+l"(d) : "l"(a), "l"(b));
}
__device__ __forceinline__ float2 unpack2(u64 p) {
    float2 r;
    asm("mov.b64 {%0, %1}, %2;" : "=f"(r.x), "=f"(r.y) : "l"(p));
    return r;
}

// ---------------- init: h = LN(0.1*feat * Win + bin) ----------------
__global__ void init_kernel(const float* __restrict__ feat, const float* __restrict__ Win,
                            const float* __restrict__ bin, const float* __restrict__ g,
                            const float* __restrict__ bln, float* __restrict__ h)
{
    __shared__ float red[4];
    __shared__ float red2[4];
    const int n = blockIdx.x;
    const int j = threadIdx.x;
    const float x = 0.1f * feat[n];
    const float val = x * Win[j] + bin[j];

    float s = val;
    #pragma unroll
    for (int o = 16; o > 0; o >>= 1) s += __shfl_xor_sync(0xffffffff, s, o);
    if ((j & 31) == 0) red[j >> 5] = s;
    __syncthreads();
    const float m = (red[0] + red[1] + red[2] + red[3]) * (1.0f / 128.0f);

    const float d = val - m;
    float s2 = d * d;
    #pragma unroll
    for (int o = 16; o > 0; o >>= 1) s2 += __shfl_xor_sync(0xffffffff, s2, o);
    if ((j & 31) == 0) red2[j >> 5] = s2;
    __syncthreads();
    const float v = (red2[0] + red2[1] + red2[2] + red2[3]) * (1.0f / 128.0f);

    h[(size_t)n * H + j] = g[j] * d * rsqrtf(v + LN_EPS) + bln[j];
}

// ---------------- CSR build ----------------
__global__ void hist_kernel(const int* __restrict__ tgt, int* __restrict__ cnt, int nE)
{
    int e = blockIdx.x * blockDim.x + threadIdx.x;
    if (e < nE) atomicAdd(&cnt[tgt[e]], 1);
}

__global__ void scan_kernel(const int* __restrict__ cnt, int* __restrict__ rowptr,
                            int* __restrict__ cursor, int n)
{
    __shared__ int wsum[32];
    __shared__ int tot_s;
    const int tid = threadIdx.x;
    const int lane = tid & 31, w = tid >> 5;
    int carry = 0;
    for (int base = 0; base < n; base += 1024) {
        const int i = base + tid;
        int x = (i < n) ? cnt[i] : 0;
        int v = x;
        #pragma unroll
        for (int off = 1; off < 32; off <<= 1) {
            int t = __shfl_up_sync(0xffffffff, v, off);
            if (lane >= off) v += t;
        }
        if (lane == 31) wsum[w] = v;
        __syncthreads();
        if (w == 0) {
            int t = wsum[lane];
            #pragma unroll
            for (int off = 1; off < 32; off <<= 1) {
                int u = __shfl_up_sync(0xffffffff, t, off);
                if (lane >= off) t += u;
            }
            wsum[lane] = t;
            if (lane == 31) tot_s = t;
        }
        __syncthreads();
        const int incl = v + (w > 0 ? wsum[w - 1] : 0);
        if (i < n) { int ex = carry + incl - x; rowptr[i] = ex; cursor[i] = ex; }
        carry += tot_s;
        __syncthreads();
    }
    if (tid == 0) rowptr[n] = carry;
}

__global__ void fill_kernel(const int* __restrict__ src, const int* __restrict__ tgt,
                            int* __restrict__ cursor, int* __restrict__ list, int nE)
{
    int e = blockIdx.x * blockDim.x + threadIdx.x;
    if (e < nE) {
        int p = atomicAdd(&cursor[tgt[e]], 1);
        list[p] = src[e];
    }
}

// ---------------- persistent weight-stationary GEMM, packed f32x2 ----------------
// out[r, c*128 + col] = act( sum_k A[r,k] * Wc[k, col] + bc[col] )
// A row: CONCAT ? concat(A0[r](128), A1[r](128)) : A0[r] (KDIM)
// Per block: 256 threads, row tile RT; thread (rg=tid/32, cg=tid%32) computes
// RT/8 rows x 4 cols per chunk; all chunk weights resident in SMEM for the launch.
template<int KDIM, int NCH, int RT, bool CONCAT, bool ACT>
__global__ void __launch_bounds__(256, 1)
pgemm_kernel(const float* __restrict__ A0, const float* __restrict__ A1,
             const float* __restrict__ W0, int ld0, const float* __restrict__ b0,
             const float* __restrict__ W1, int ld1, const float* __restrict__ b1,
             const float* __restrict__ W2, int ld2, const float* __restrict__ b2,
             float* __restrict__ out, int outW, int nRows)
{
    constexpr int RPT = RT >> 3;     // rows per thread
    constexpr int NP  = RPT >> 1;    // packed row-pairs per thread
    constexpr int XST = RT + 4;      // XsT stride (floats)

    extern __shared__ float sm[];
    float* Ws  = sm;                       // NCH * KDIM * 128
    float* XsT = sm + NCH * KDIM * 128;    // KDIM * XST

    const int tid = threadIdx.x;
    const float* Wp[3] = {W0, W1, W2};
    const int ldw[3] = {ld0, ld1, ld2};
    const float* bp[3] = {b0, b1, b2};

    #pragma unroll
    for (int c = 0; c < NCH; c++) {
        const float* w = Wp[c];
        const int l = ldw[c];
        for (int idx = tid; idx < KDIM * 128; idx += 256)
            Ws[c * KDIM * 128 + idx] = w[(size_t)(idx >> 7) * l + (idx & 127)];
    }

    const int cg = tid & 31;
    const int rg = tid >> 5;
    float4 bias[NCH];
    #pragma unroll
    for (int c = 0; c < NCH; c++)
        bias[c] = bp[c] ? *(const float4*)&bp[c][4 * cg] : make_float4(0.f, 0.f, 0.f, 0.f);

    __syncthreads();

    const int nTiles = (nRows + RT - 1) / RT;
    for (int tile = blockIdx.x; tile < nTiles; tile += gridDim.x) {
        const int row0 = tile * RT;
        for (int idx = tid; idx < RT * KDIM; idx += 256) {
            const int e = idx / KDIM;
            const int k = idx % KDIM;
            int r = row0 + e;
            if (r >= nRows) r = nRows - 1;
            float v;
            if (CONCAT) v = (k < 128) ? A0[(size_t)r * 128 + k] : A1[(size_t)r * 128 + (k - 128)];
            else        v = A0[(size_t)r * KDIM + k];
            XsT[k * XST + e] = v;
        }
        __syncthreads();

        #pragma unroll
        for (int c = 0; c < NCH; c++) {
            const float* Wsc = Ws + c * KDIM * 128;
            u64 acc[NP][4];
            #pragma unroll
            for (int p = 0; p < NP; p++) {
                acc[p][0] = pack2(bias[c].x, bias[c].x);
                acc[p][1] = pack2(bias[c].y, bias[c].y);
                acc[p][2] = pack2(bias[c].z, bias[c].z);
                acc[p][3] = pack2(bias[c].w, bias[c].w);
            }

            #pragma unroll 8
            for (int k = 0; k < KDIM; k++) {
                float xv[RPT];
                #pragma unroll
                for (int q = 0; q < RPT / 4; q++) {
                    const float4 t = *(const float4*)&XsT[k * XST + RPT * rg + 4 * q];
                    xv[4 * q + 0] = t.x; xv[4 * q + 1] = t.y;
                    xv[4 * q + 2] = t.z; xv[4 * q + 3] = t.w;
                }
                const float4 w = *(const float4*)&Wsc[k * 128 + 4 * cg];
                u64 xp[NP];
                #pragma unroll
                for (int p = 0; p < NP; p++) xp[p] = pack2(xv[2 * p], xv[2 * p + 1]);
                const u64 wd0 = pack2(w.x, w.x);
                const u64 wd1 = pack2(w.y, w.y);
                const u64 wd2 = pack2(w.z, w.z);
                const u64 wd3 = pack2(w.w, w.w);
                #pragma unroll
                for (int p = 0; p < NP; p++) {
                    fma2(acc[p][0], xp[p], wd0);
                    fma2(acc[p][1], xp[p], wd1);
                    fma2(acc[p][2], xp[p], wd2);
                    fma2(acc[p][3], xp[p], wd3);
                }
            }

            #pragma unroll
            for (int p = 0; p < NP; p++) {
                const float2 v0 = unpack2(acc[p][0]);
                const float2 v1 = unpack2(acc[p][1]);
                const float2 v2 = unpack2(acc[p][2]);
                const float2 v3 = unpack2(acc[p][3]);
                const int r0 = row0 + RPT * rg + 2 * p;
                if (r0 < nRows) {
                    float4 o;
                    o.x = ACT ? elu_f(v0.x) : v0.x;
                    o.y = ACT ? elu_f(v1.x) : v1.x;
                    o.z = ACT ? elu_f(v2.x) : v2.x;
                    o.w = ACT ? elu_f(v3.x) : v3.x;
                    *(float4*)&out[(size_t)r0 * outW + c * 128 + 4 * cg] = o;
                }
                if (r0 + 1 < nRows) {
                    float4 o;
                    o.x = ACT ? elu_f(v0.y) : v0.y;
                    o.y = ACT ? elu_f(v1.y) : v1.y;
                    o.z = ACT ? elu_f(v2.y) : v2.y;
                    o.w = ACT ? elu_f(v3.y) : v3.y;
                    *(float4*)&out[(size_t)(r0 + 1) * outW + c * 128 + 4 * cg] = o;
                }
            }
        }
        __syncthreads();
    }
}

// ---------------- aggregate: out[t] = sum_{e in CSR(t)} elu(Psend[src_e] + Ptgt[t] + b) ----------------
__global__ void agg_kernel(const int* __restrict__ rowptr, const int* __restrict__ srcs,
                           const float* __restrict__ Psend, const float* __restrict__ Ptgt,
                           const float* __restrict__ bias, float* __restrict__ out)
{
    const int t = blockIdx.x;
    const int j = threadIdx.x;
    const float base = Ptgt[(size_t)t * 256 + 128 + j] + bias[j];
    const int beg = rowptr[t], end = rowptr[t + 1];
    float s0 = 0.f, s1 = 0.f;
    int i = beg;
    for (; i + 1 < end; i += 2) {
        const int a = srcs[i];
        const int b = srcs[i + 1];
        s0 += elu_f(base + Psend[(size_t)a * 256 + j]);
        s1 += elu_f(base + Psend[(size_t)b * 256 + j]);
    }
    if (i < end) s0 += elu_f(base + Psend[(size_t)srcs[i] * 256 + j]);
    out[(size_t)t * 128 + j] = s0 + s1;
}

// ---------------- GRU combine: h <- z*h + (1-z)*tanh(xah + r*hah) ----------------
__global__ void gru_combine_kernel(const float* __restrict__ xa, const float* __restrict__ ha,
                                   float* __restrict__ h, int nNodes)
{
    const int idx = blockIdx.x * blockDim.x + threadIdx.x;
    if (idx >= nNodes * 32) return;
    const int n = idx >> 5;
    const int q = (idx & 31) * 4;
    const float4 xz = *(const float4*)&xa[(size_t)n * 384 + q];
    const float4 xr = *(const float4*)&xa[(size_t)n * 384 + 128 + q];
    const float4 xh = *(const float4*)&xa[(size_t)n * 384 + 256 + q];
    const float4 hz = *(const float4*)&ha[(size_t)n * 384 + q];
    const float4 hr = *(const float4*)&ha[(size_t)n * 384 + 128 + q];
    const float4 hh = *(const float4*)&ha[(size_t)n * 384 + 256 + q];
    float4 ho = *(const float4*)&h[(size_t)n * 128 + q];

    float z, r, c;
    z = sig_f(xz.x + hz.x); r = sig_f(xr.x + hr.x); c = tanhf(xh.x + r * hh.x); ho.x = z * ho.x + (1.f - z) * c;
    z = sig_f(xz.y + hz.y); r = sig_f(xr.y + hr.y); c = tanhf(xh.y + r * hh.y); ho.y = z * ho.y + (1.f - z) * c;
    z = sig_f(xz.z + hz.z); r = sig_f(xr.z + hr.z); c = tanhf(xh.z + r * hh.z); ho.z = z * ho.z + (1.f - z) * c;
    z = sig_f(xz.w + hz.w); r = sig_f(xr.w + hr.w); c = tanhf(xh.w + r * hh.w); ho.w = z * ho.w + (1.f - z) * c;
    *(float4*)&h[(size_t)n * 128 + q] = ho;
}

// ---------------- final: out[n] = hv[n] . Wf + bf ----------------
__global__ void final_kernel(const float* __restrict__ hv, const float* __restrict__ Wf,
                             const float* __restrict__ bf, float* __restrict__ out, int n)
{
    const int gw = (blockIdx.x * blockDim.x + threadIdx.x) >> 5;
    const int lane = threadIdx.x & 31;
    if (gw >= n) return;
    const float* row = hv + (size_t)gw * H;
    float s = row[lane] * Wf[lane] + row[lane + 32] * Wf[lane + 32]
            + row[lane + 64] * Wf[lane + 64] + row[lane + 96] * Wf[lane + 96];
    #pragma unroll
    for (int o = 16; o > 0; o >>= 1) s += __shfl_xor_sync(0xffffffff, s, o);
    if (lane == 0) out[gw] = s + bf[0];
}

// ---------------- host ----------------
#define SMEM_MSG  ((2 * 128 * 128 + 128 * 68) * 4)          // 165,888
#define SMEM_NODE ((1 * 256 * 128 + 256 * 68) * 4)          // 200,704
#define SMEM_GRU  ((3 * 128 * 128 + 128 * 36) * 4)          // 215,040

static inline int mini(int a, int b) { return a < b ? a : b; }

extern "C" void kernel_launch(void* const* d_in, const int* in_sizes, int n_in,
                              void* d_out, int out_size)
{
    const float* check_feats = (const float*)d_in[0];
    const float* var_feats   = (const float*)d_in[1];
    const int*   c2v_src     = (const int*)d_in[2];
    const int*   c2v_tgt     = (const int*)d_in[3];
    const int*   v2c_src     = (const int*)d_in[4];
    const int*   v2c_tgt     = (const int*)d_in[5];
    const float* Wc_in  = (const float*)d_in[6];
    const float* bc_in  = (const float*)d_in[7];
    const float* Wv_in  = (const float*)d_in[8];
    const float* bv_in  = (const float*)d_in[9];
    const float* gc_ln  = (const float*)d_in[10];
    const float* bc_ln  = (const float*)d_in[11];
    const float* gv_ln  = (const float*)d_in[12];
    const float* bv_ln  = (const float*)d_in[13];
    const float* Wmsg_c = (const float*)d_in[14];
    const float* bmsg_c = (const float*)d_in[15];
    const float* Wmsg_v = (const float*)d_in[16];
    const float* bmsg_v = (const float*)d_in[17];
    const float* Wns_c  = (const float*)d_in[18];
    const float* bns_c  = (const float*)d_in[19];
    const float* Wns_v  = (const float*)d_in[20];
    const float* bns_v  = (const float*)d_in[21];
    const float* Wg_c   = (const float*)d_in[22];
    const float* Ug_c   = (const float*)d_in[23];
    const float* bg_c   = (const float*)d_in[24];
    const float* Wg_v   = (const float*)d_in[25];
    const float* Ug_v   = (const float*)d_in[26];
    const float* bg_v   = (const float*)d_in[27];
    const float* Wf     = (const float*)d_in[28];
    const float* bf     = (const float*)d_in[29];

    const int NCn = in_sizes[0];  // 8000
    const int NVn = in_sizes[1];  // 16000
    const int E   = in_sizes[2];  // 60000

    float *hc, *hv, *Pc, *Pv, *aggc, *aggv, *updc, *updv, *xac, *hac, *xav, *hav;
    int *cnt_c, *cnt_v, *rp_c, *rp_v, *cur_c, *cur_v, *el_c, *el_v;
    cudaGetSymbolAddress((void**)&hc,   g_hc);
    cudaGetSymbolAddress((void**)&hv,   g_hv);
    cudaGetSymbolAddress((void**)&Pc,   g_Pc);
    cudaGetSymbolAddress((void**)&Pv,   g_Pv);
    cudaGetSymbolAddress((void**)&aggc, g_aggc);
    cudaGetSymbolAddress((void**)&aggv, g_aggv);
    cudaGetSymbolAddress((void**)&updc, g_updc);
    cudaGetSymbolAddress((void**)&updv, g_updv);
    cudaGetSymbolAddress((void**)&xac,  g_xac);
    cudaGetSymbolAddress((void**)&hac,  g_hac);
    cudaGetSymbolAddress((void**)&xav,  g_xav);
    cudaGetSymbolAddress((void**)&hav,  g_hav);
    cudaGetSymbolAddress((void**)&cnt_c, g_cnt_c);
    cudaGetSymbolAddress((void**)&cnt_v, g_cnt_v);
    cudaGetSymbolAddress((void**)&rp_c,  g_rp_c);
    cudaGetSymbolAddress((void**)&rp_v,  g_rp_v);
    cudaGetSymbolAddress((void**)&cur_c, g_cur_c);
    cudaGetSymbolAddress((void**)&cur_v, g_cur_v);
    cudaGetSymbolAddress((void**)&el_c,  g_el_c);
    cudaGetSymbolAddress((void**)&el_v,  g_el_v);

    auto msgGemm  = pgemm_kernel<128, 2, 64, false, false>;
    auto nodeGemm = pgemm_kernel<256, 1, 64, true,  true>;
    auto gruGemm  = pgemm_kernel<128, 3, 32, false, false>;
    cudaFuncSetAttribute(msgGemm,  cudaFuncAttributeMaxDynamicSharedMemorySize, SMEM_MSG);
    cudaFuncSetAttribute(nodeGemm, cudaFuncAttributeMaxDynamicSharedMemorySize, SMEM_NODE);
    cudaFuncSetAttribute(gruGemm,  cudaFuncAttributeMaxDynamicSharedMemorySize, SMEM_GRU);

    // ---- init node states ----
    init_kernel<<<NCn, 128>>>(check_feats, Wc_in, bc_in, gc_ln, bc_ln, hc);
    init_kernel<<<NVn, 128>>>(var_feats,  Wv_in, bv_in, gv_ln, bv_ln, hv);

    // ---- build CSR (per direction, once per launch) ----
    const int gEh = (E + 255) / 256;
    cudaMemsetAsync(cnt_c, 0, NCn * sizeof(int), 0);
    cudaMemsetAsync(cnt_v, 0, NVn * sizeof(int), 0);
    hist_kernel<<<gEh, 256>>>(v2c_tgt, cnt_c, E);   // v2c keyed by check target
    hist_kernel<<<gEh, 256>>>(c2v_tgt, cnt_v, E);   // c2v keyed by var target
    scan_kernel<<<1, 1024>>>(cnt_c, rp_c, cur_c, NCn);
    scan_kernel<<<1, 1024>>>(cnt_v, rp_v, cur_v, NVn);
    fill_kernel<<<gEh, 256>>>(v2c_src, v2c_tgt, cur_c, el_c, E);
    fill_kernel<<<gEh, 256>>>(c2v_src, c2v_tgt, cur_v, el_v, E);

    const int tMsgV  = (NVn + 63) / 64, tMsgC  = (NCn + 63) / 64;
    const int tNodeV = tMsgV,           tNodeC = tMsgC;
    const int tGruV  = (NVn + 31) / 32, tGruC  = (NCn + 31) / 32;

    for (int it = 0; it < NITER; it++) {
        // message projections:
        // Pv = hv @ [Wmsg_c_top | Wmsg_v_bot]   (sender for v2c | receiver for c2v)
        msgGemm<<<mini(tMsgV, 148), 256, SMEM_MSG>>>(
            hv, nullptr,
            Wmsg_c, 128, nullptr,
            Wmsg_v + 128 * 128, 128, nullptr,
            nullptr, 0, nullptr,
            Pv, 256, NVn);
        // Pc = hc @ [Wmsg_v_top | Wmsg_c_bot]   (sender for c2v | receiver for v2c)
        msgGemm<<<mini(tMsgC, 148), 256, SMEM_MSG>>>(
            hc, nullptr,
            Wmsg_v, 128, nullptr,
            Wmsg_c + 128 * 128, 128, nullptr,
            nullptr, 0, nullptr,
            Pc, 256, NCn);

        // aggregate (deterministic gather-sum over CSR, no atomics)
        agg_kernel<<<NCn, 128>>>(rp_c, el_c, Pv, Pc, bmsg_c, aggc);
        agg_kernel<<<NVn, 128>>>(rp_v, el_v, Pc, Pv, bmsg_v, aggv);

        // node update: upd = elu(concat(h, agg) @ Wns + b)
        nodeGemm<<<mini(tNodeC, 148), 256, SMEM_NODE>>>(
            hc, aggc, Wns_c, 128, bns_c,
            nullptr, 0, nullptr, nullptr, 0, nullptr,
            updc, 128, NCn);
        nodeGemm<<<mini(tNodeV, 148), 256, SMEM_NODE>>>(
            hv, aggv, Wns_v, 128, bns_v,
            nullptr, 0, nullptr, nullptr, 0, nullptr,
            updv, 128, NVn);

        // GRU gate pre-activations: xa = upd@Wg + b0, ha = h@Ug + b1 (3 gate chunks)
        gruGemm<<<mini(tGruC, 148), 256, SMEM_GRU>>>(
            updc, nullptr,
            Wg_c, 384, bg_c,
            Wg_c + 128, 384, bg_c + 128,
            Wg_c + 256, 384, bg_c + 256,
            xac, 384, NCn);
        gruGemm<<<mini(tGruC, 148), 256, SMEM_GRU>>>(
            hc, nullptr,
            Ug_c, 384, bg_c + 384,
            Ug_c + 128, 384, bg_c + 384 + 128,
            Ug_c + 256, 384, bg_c + 384 + 256,
            hac, 384, NCn);
        gru_combine_kernel<<<(NCn * 32 + 255) / 256, 256>>>(xac, hac, hc, NCn);

        gruGemm<<<mini(tGruV, 148), 256, SMEM_GRU>>>(
            updv, nullptr,
            Wg_v, 384, bg_v,
            Wg_v + 128, 384, bg_v + 128,
            Wg_v + 256, 384, bg_v + 256,
            xav, 384, NVn);
        gruGemm<<<mini(tGruV, 148), 256, SMEM_GRU>>>(
            hv, nullptr,
            Ug_v, 384, bg_v + 384,
            Ug_v + 128, 384, bg_v + 384 + 128,
            Ug_v + 256, 384, bg_v + 384 + 256,
            hav, 384, NVn);
        gru_combine_kernel<<<(NVn * 32 + 255) / 256, 256>>>(xav, hav, hv, NVn);
    }

    final_kernel<<<(NVn * 32 + 127) / 128, 128>>>(hv, Wf, bf, (float*)d_out, NVn);
}